// round 2
// baseline (speedup 1.0000x reference)
#include <cuda_runtime.h>

// Problem constants (shapes fixed by setup_inputs)
#define LRES 1024
#define TOPK 48
#define EF   416     // 16 pos + 16 rbf(Dnb) + 24*16 pair rbf
#define SF   1280    // 5*32*8
#define KT   16      // edges per block in E_s kernel
#define NTILE 3      // 48 / KT

// Output layout: flattened tuple (E, E_idx, E_s, E_idx_sub), all as float32
#define OFF_E       0ull
#define OFF_EIDX    6291456ull               // 1024*48*128
#define OFF_ES      6340608ull               // + 1024*48
#define OFF_EIDXSUB 12632064ull              // + 1024*48*128

// scratch (static device globals: no allocations allowed)
__device__ float g_coords[LRES * 15];        // N,Ca,C,O,Cb  (5 atoms x 3)
__device__ int   g_eidx[LRES * TOPK];
__device__ float g_dnb[LRES * TOPK];

__device__ __forceinline__ unsigned long long u64min_(unsigned long long a,
                                                      unsigned long long b) {
    return a < b ? a : b;
}

// ---------------------------------------------------------------------------
// Kernel 1: per-residue geometry (virtual Cb)
// ---------------------------------------------------------------------------
__global__ void geom_kernel(const float* __restrict__ X) {
    int i = blockIdx.x * blockDim.x + threadIdx.x;
    if (i >= LRES) return;
    const float* xi = X + (size_t)i * 37 * 3;
    float n0 = xi[0],  n1 = xi[1],  n2 = xi[2];    // N   = atom 0
    float a0 = xi[3],  a1 = xi[4],  a2 = xi[5];    // Ca  = atom 1
    float c0 = xi[6],  c1 = xi[7],  c2 = xi[8];    // C   = atom 2
    float o0 = xi[12], o1 = xi[13], o2 = xi[14];   // O   = atom 4
    float b0 = a0 - n0, b1 = a1 - n1, b2 = a2 - n2;       // b = Ca - N
    float d0 = c0 - a0, d1 = c1 - a1, d2 = c2 - a2;       // c = C - Ca
    float x0 = b1 * d2 - b2 * d1;                          // a = b x c
    float x1 = b2 * d0 - b0 * d2;
    float x2 = b0 * d1 - b1 * d0;
    float cb0 = -0.58273431f * x0 + 0.56802827f * b0 - 0.54067466f * d0 + a0;
    float cb1 = -0.58273431f * x1 + 0.56802827f * b1 - 0.54067466f * d1 + a1;
    float cb2 = -0.58273431f * x2 + 0.56802827f * b2 - 0.54067466f * d2 + a2;
    float* dst = g_coords + i * 15;
    dst[0] = n0;  dst[1] = n1;  dst[2] = n2;      // slot 0: N
    dst[3] = a0;  dst[4] = a1;  dst[5] = a2;      // slot 1: Ca
    dst[6] = c0;  dst[7] = c1;  dst[8] = c2;      // slot 2: C
    dst[9] = o0;  dst[10] = o1; dst[11] = o2;     // slot 3: O
    dst[12] = cb0; dst[13] = cb1; dst[14] = cb2;  // slot 4: Cb
}

// ---------------------------------------------------------------------------
// Kernel 2: per-residue top-k (48 smallest D_adj, tie -> smallest index)
// Exactly replicates jax.lax.top_k(-D_adj, 48) ordering.
// ---------------------------------------------------------------------------
__global__ void topk_kernel(const float* __restrict__ X,
                            const float* __restrict__ mask,
                            float* __restrict__ out) {
    __shared__ float dsh[LRES];
    __shared__ unsigned long long keys[LRES];
    __shared__ float wmaxs[8];
    __shared__ unsigned long long wmins[8];
    __shared__ float smDmax;

    int i = blockIdx.x;
    int tid = threadIdx.x;
    float cax = X[((size_t)i * 37 + 1) * 3 + 0];
    float cay = X[((size_t)i * 37 + 1) * 3 + 1];
    float caz = X[((size_t)i * 37 + 1) * 3 + 2];
    float mi = mask[i];

    float lmax = 0.0f;
    for (int j = tid; j < LRES; j += 256) {
        float dx = cax - X[((size_t)j * 37 + 1) * 3 + 0];
        float dy = cay - X[((size_t)j * 37 + 1) * 3 + 1];
        float dz = caz - X[((size_t)j * 37 + 1) * 3 + 2];
        float s = dx * dx + dy * dy + dz * dz;
        float m2 = mi * mask[j];
        float Dv = m2 * sqrtf(s + 1e-6f);
        dsh[j] = Dv;
        lmax = fmaxf(lmax, Dv);
    }
    for (int off = 16; off; off >>= 1)
        lmax = fmaxf(lmax, __shfl_xor_sync(0xffffffffu, lmax, off));
    if ((tid & 31) == 0) wmaxs[tid >> 5] = lmax;
    __syncthreads();
    if (tid == 0) {
        float m = wmaxs[0];
        #pragma unroll
        for (int w = 1; w < 8; w++) m = fmaxf(m, wmaxs[w]);
        smDmax = m;
    }
    __syncthreads();
    float Dmax = smDmax;

    for (int j = tid; j < LRES; j += 256) {
        float m2 = mi * mask[j];
        float Dadj = dsh[j] + (1.0f - m2) * Dmax;
        keys[j] = (((unsigned long long)__float_as_uint(Dadj)) << 32) |
                  (unsigned int)j;
    }
    __syncthreads();

    for (int sel = 0; sel < TOPK; sel++) {
        unsigned long long lmin = 0xffffffffffffffffull;
        #pragma unroll
        for (int c = 0; c < 4; c++) lmin = u64min_(lmin, keys[tid + 256 * c]);
        for (int off = 16; off; off >>= 1) {
            unsigned long long o2 = __shfl_xor_sync(0xffffffffu, lmin, off);
            lmin = u64min_(lmin, o2);
        }
        if ((tid & 31) == 0) wmins[tid >> 5] = lmin;
        __syncthreads();
        if (tid == 0) {
            unsigned long long m = wmins[0];
            #pragma unroll
            for (int w = 1; w < 8; w++) m = u64min_(m, wmins[w]);
            int j = (int)(m & 0xffffffffull);
            float dv = __uint_as_float((unsigned int)(m >> 32));
            g_eidx[i * TOPK + sel] = j;
            g_dnb[i * TOPK + sel] = dv;
            out[OFF_EIDX + (size_t)i * TOPK + sel] = (float)j;
            out[OFF_EIDXSUB + (size_t)i * TOPK + sel] = (float)j;
            keys[j] = 0xffffffffffffffffull;
        }
        __syncthreads();
    }
}

// ---------------------------------------------------------------------------
// Kernel 3: E = LN( concat(pos16, rbf16(Dnb), 24x rbf16(pair)) @ W_e^T )
// One block per residue (48 edges), 128 threads = output channels.
// ---------------------------------------------------------------------------
__global__ void __launch_bounds__(128) e_kernel(
    const float* __restrict__ Wpos, const float* __restrict__ bpos,
    const int* __restrict__ ridx, const int* __restrict__ clab,
    const float* __restrict__ We, const float* __restrict__ ge,
    const float* __restrict__ be, float* __restrict__ out) {
    extern __shared__ float feats[];  // TOPK * EF floats (79872 B)
    int i = blockIdx.x;
    int tid = threadIdx.x;

    // positional (16) + rbf of D_neighbors (16)
    if (tid < TOPK) {
        int k = tid;
        int j = g_eidx[i * TOPK + k];
        int offr = ridx[i] - ridx[j];
        int ec = (clab[i] == clab[j]) ? 1 : 0;
        int d = min(max(offr + 32, 0), 64) * ec + (1 - ec) * 65;
        float* fr = feats + k * EF;
        #pragma unroll
        for (int f = 0; f < 16; f++) fr[f] = Wpos[f * 66 + d] + bpos[f];
        float D = g_dnb[i * TOPK + k];
        #pragma unroll
        for (int r = 0; r < 16; r++) {
            float t = (D - (2.0f + (float)r * (20.0f / 15.0f))) * 0.8f;
            fr[16 + r] = __expf(-t * t);
        }
    }

    // 24 atom-pair distances x rbf16
    const signed char pa[24] = {0,2,3,4,1,1,1,1,0,0,0,4,4,3,0,2,3,4,2,3,4,2,3,2};
    const signed char pb[24] = {0,2,3,4,0,2,3,4,2,3,4,2,3,2,1,1,1,1,0,0,0,4,4,3};
    for (int tt = tid; tt < TOPK * 24; tt += 128) {
        int k = tt / 24, p = tt - k * 24;
        int j = g_eidx[i * TOPK + k];
        const float* A = g_coords + i * 15 + (int)pa[p] * 3;
        const float* B = g_coords + j * 15 + (int)pb[p] * 3;
        float dx = A[0] - B[0], dy = A[1] - B[1], dz = A[2] - B[2];
        float D = sqrtf(dx * dx + dy * dy + dz * dz + 1e-6f);
        float* fr = feats + k * EF + 32 + p * 16;
        #pragma unroll
        for (int r = 0; r < 16; r++) {
            float t = (D - (2.0f + (float)r * (20.0f / 15.0f))) * 0.8f;
            fr[r] = __expf(-t * t);
        }
    }
    __syncthreads();

    // matvec: 128 channels, each thread owns one W_e row, 48 accumulators
    int o = tid;
    float acc[TOPK];
    #pragma unroll
    for (int k = 0; k < TOPK; k++) acc[k] = 0.0f;
    const float4* Wr = (const float4*)(We + (size_t)o * EF);
    for (int f8 = 0; f8 < EF / 8; f8++) {
        float4 w0 = Wr[2 * f8];
        float4 w1 = Wr[2 * f8 + 1];
        #pragma unroll
        for (int k = 0; k < TOPK; k++) {
            const float4* fp = (const float4*)(feats + k * EF + f8 * 8);
            float4 v0 = fp[0], v1 = fp[1];
            acc[k] = fmaf(w0.x, v0.x, acc[k]);
            acc[k] = fmaf(w0.y, v0.y, acc[k]);
            acc[k] = fmaf(w0.z, v0.z, acc[k]);
            acc[k] = fmaf(w0.w, v0.w, acc[k]);
            acc[k] = fmaf(w1.x, v1.x, acc[k]);
            acc[k] = fmaf(w1.y, v1.y, acc[k]);
            acc[k] = fmaf(w1.z, v1.z, acc[k]);
            acc[k] = fmaf(w1.w, v1.w, acc[k]);
        }
    }
    __syncthreads();

    // LayerNorm over 128 channels per edge (reuse smem)
    float* h = feats;  // 48*128 floats
    #pragma unroll
    for (int k = 0; k < TOPK; k++) h[k * 128 + o] = acc[k];
    __syncthreads();

    int wid = tid >> 5, lane = tid & 31;
    for (int k = wid; k < TOPK; k += 4) {
        float v0 = h[k * 128 + lane];
        float v1 = h[k * 128 + lane + 32];
        float v2 = h[k * 128 + lane + 64];
        float v3 = h[k * 128 + lane + 96];
        float s = v0 + v1 + v2 + v3;
        for (int off = 16; off; off >>= 1) s += __shfl_xor_sync(0xffffffffu, s, off);
        float mu = s * (1.0f / 128.0f);
        float d0 = v0 - mu, d1 = v1 - mu, d2 = v2 - mu, d3 = v3 - mu;
        float s2 = d0 * d0 + d1 * d1 + d2 * d2 + d3 * d3;
        for (int off = 16; off; off >>= 1) s2 += __shfl_xor_sync(0xffffffffu, s2, off);
        float inv = rsqrtf(s2 * (1.0f / 128.0f) + 1e-5f);
        size_t base = OFF_E + ((size_t)(i * TOPK + k)) * 128;
        out[base + lane]      = ge[lane]      * d0 * inv + be[lane];
        out[base + lane + 32] = ge[lane + 32] * d1 * inv + be[lane + 32];
        out[base + lane + 64] = ge[lane + 64] * d2 * inv + be[lane + 64];
        out[base + lane + 96] = ge[lane + 96] * d3 * inv + be[lane + 96];
    }
}

// ---------------------------------------------------------------------------
// Kernel 4: E_s = LN( rbf8(anchor-sidechain dists)*am @ W_s^T )
// One block per (residue, 16-edge tile), 128 threads = channels.
// ---------------------------------------------------------------------------
__global__ void __launch_bounds__(128) es_kernel(
    const float* __restrict__ X, const float* __restrict__ amask,
    const float* __restrict__ Ws, const float* __restrict__ gs,
    const float* __restrict__ bs, float* __restrict__ out) {
    extern __shared__ float feats[];  // KT * SF floats (81920 B)
    __shared__ int jn[KT];
    __shared__ float anch[15];

    int bx = blockIdx.x;
    int i = bx / NTILE;
    int k0 = (bx - i * NTILE) * KT;
    int tid = threadIdx.x;

    if (tid < KT) jn[tid] = g_eidx[i * TOPK + k0 + tid];
    if (tid >= 32 && tid < 47) anch[tid - 32] = g_coords[i * 15 + (tid - 32)];
    __syncthreads();

    // KT*5*32 distances -> 8 rbf bins each, scaled by neighbor atom mask
    for (int tt = tid; tt < KT * 160; tt += 128) {
        int kk = tt / 160;
        int rem = tt - kk * 160;
        int a = rem >> 5, s = rem & 31;
        int j = jn[kk];
        const float* Sp = X + ((size_t)j * 37 + 5 + s) * 3;
        float dx = anch[a * 3 + 0] - Sp[0];
        float dy = anch[a * 3 + 1] - Sp[1];
        float dz = anch[a * 3 + 2] - Sp[2];
        float D = sqrtf(dx * dx + dy * dy + dz * dz + 1e-6f);
        float m = amask[(size_t)j * 37 + 5 + s];
        float* fr = feats + kk * SF + (a * 32 + s) * 8;
        #pragma unroll
        for (int r = 0; r < 8; r++) {
            float t = (D - (2.0f + (float)r * (20.0f / 7.0f))) * 0.4f;
            fr[r] = m * __expf(-t * t);
        }
    }
    __syncthreads();

    int o = tid;
    float acc[KT];
    #pragma unroll
    for (int kk = 0; kk < KT; kk++) acc[kk] = 0.0f;
    const float4* Wr = (const float4*)(Ws + (size_t)o * SF);
    for (int f8 = 0; f8 < SF / 8; f8++) {
        float4 w0 = Wr[2 * f8];
        float4 w1 = Wr[2 * f8 + 1];
        #pragma unroll
        for (int kk = 0; kk < KT; kk++) {
            const float4* fp = (const float4*)(feats + kk * SF + f8 * 8);
            float4 v0 = fp[0], v1 = fp[1];
            acc[kk] = fmaf(w0.x, v0.x, acc[kk]);
            acc[kk] = fmaf(w0.y, v0.y, acc[kk]);
            acc[kk] = fmaf(w0.z, v0.z, acc[kk]);
            acc[kk] = fmaf(w0.w, v0.w, acc[kk]);
            acc[kk] = fmaf(w1.x, v1.x, acc[kk]);
            acc[kk] = fmaf(w1.y, v1.y, acc[kk]);
            acc[kk] = fmaf(w1.z, v1.z, acc[kk]);
            acc[kk] = fmaf(w1.w, v1.w, acc[kk]);
        }
    }
    __syncthreads();

    float* h = feats;  // KT*128
    #pragma unroll
    for (int kk = 0; kk < KT; kk++) h[kk * 128 + o] = acc[kk];
    __syncthreads();

    int wid = tid >> 5, lane = tid & 31;
    for (int kk = wid; kk < KT; kk += 4) {
        float v0 = h[kk * 128 + lane];
        float v1 = h[kk * 128 + lane + 32];
        float v2 = h[kk * 128 + lane + 64];
        float v3 = h[kk * 128 + lane + 96];
        float s = v0 + v1 + v2 + v3;
        for (int off = 16; off; off >>= 1) s += __shfl_xor_sync(0xffffffffu, s, off);
        float mu = s * (1.0f / 128.0f);
        float d0 = v0 - mu, d1 = v1 - mu, d2 = v2 - mu, d3 = v3 - mu;
        float s2 = d0 * d0 + d1 * d1 + d2 * d2 + d3 * d3;
        for (int off = 16; off; off >>= 1) s2 += __shfl_xor_sync(0xffffffffu, s2, off);
        float inv = rsqrtf(s2 * (1.0f / 128.0f) + 1e-5f);
        size_t base = OFF_ES + ((size_t)(i * TOPK + k0 + kk)) * 128;
        out[base + lane]      = gs[lane]      * d0 * inv + bs[lane];
        out[base + lane + 32] = gs[lane + 32] * d1 * inv + bs[lane + 32];
        out[base + lane + 64] = gs[lane + 64] * d2 * inv + bs[lane + 64];
        out[base + lane + 96] = gs[lane + 96] * d3 * inv + bs[lane + 96];
    }
}

// ---------------------------------------------------------------------------
extern "C" void kernel_launch(void* const* d_in, const int* in_sizes, int n_in,
                              void* d_out, int out_size) {
    (void)in_sizes; (void)n_in; (void)out_size;
    const float* X     = (const float*)d_in[0];
    // d_in[1] = L (unused), d_in[5] = dihedral_mask (unused by reference)
    const float* mask  = (const float*)d_in[2];
    const float* amask = (const float*)d_in[3];
    const int*   ridx  = (const int*)d_in[4];
    const int*   clab  = (const int*)d_in[6];
    const float* Wpos  = (const float*)d_in[7];
    const float* bpos  = (const float*)d_in[8];
    const float* We    = (const float*)d_in[9];
    const float* ge    = (const float*)d_in[10];
    const float* be    = (const float*)d_in[11];
    const float* Ws    = (const float*)d_in[12];
    const float* gs    = (const float*)d_in[13];
    const float* bs    = (const float*)d_in[14];
    float* out = (float*)d_out;

    cudaFuncSetAttribute(e_kernel, cudaFuncAttributeMaxDynamicSharedMemorySize,
                         TOPK * EF * (int)sizeof(float));
    cudaFuncSetAttribute(es_kernel, cudaFuncAttributeMaxDynamicSharedMemorySize,
                         KT * SF * (int)sizeof(float));

    geom_kernel<<<(LRES + 255) / 256, 256>>>(X);
    topk_kernel<<<LRES, 256>>>(X, mask, out);
    e_kernel<<<LRES, 128, TOPK * EF * sizeof(float)>>>(Wpos, bpos, ridx, clab,
                                                       We, ge, be, out);
    es_kernel<<<LRES * NTILE, 128, KT * SF * sizeof(float)>>>(X, amask, Ws, gs,
                                                              bs, out);
}